// round 1
// baseline (speedup 1.0000x reference)
#include <cuda_runtime.h>

#define BB    32
#define TT    12
#define NNODE 5000
#define CCH   8
#define EEDGE 5000
#define MEDGE 160000
#define LAMW  0.3f
#define EPSW  1e-8f

// normalized features, layout (node, b, 16)
__device__ float g_fhat[(size_t)NNODE * BB * 16];
// segment accumulators, layout (e, b)
__device__ float g_acc[(size_t)EEDGE * BB];

// ---------------------------------------------------------------------------
// Kernel 1: per-(b,n) compute mean/std over T, normalize 16-vector, store fhat
// ---------------------------------------------------------------------------
__global__ void feat_kernel(const float* __restrict__ x) {
    int tid = blockIdx.x * blockDim.x + threadIdx.x;
    if (tid >= BB * NNODE) return;
    int b = tid / NNODE;
    int n = tid - b * NNODE;

    float s[CCH], sq[CCH];
#pragma unroll
    for (int k = 0; k < CCH; k++) { s[k] = 0.f; sq[k] = 0.f; }

#pragma unroll
    for (int t = 0; t < TT; t++) {
        const float4* p = reinterpret_cast<const float4*>(
            x + (((size_t)b * TT + t) * NNODE + n) * CCH);
        float4 a = p[0];
        float4 c = p[1];
        float v[CCH] = {a.x, a.y, a.z, a.w, c.x, c.y, c.z, c.w};
#pragma unroll
        for (int k = 0; k < CCH; k++) {
            s[k] += v[k];
            sq[k] = fmaf(v[k], v[k], sq[k]);
        }
    }

    float f[16];
    float nrm2 = 0.f;
#pragma unroll
    for (int k = 0; k < CCH; k++) {
        float m   = s[k] * (1.0f / TT);
        float var = (sq[k] - (float)TT * m * m) * (1.0f / (TT - 1));
        float sd  = sqrtf(fmaxf(var, 0.f));
        f[k]       = m;
        f[CCH + k] = sd;
    }
#pragma unroll
    for (int k = 0; k < 16; k++) nrm2 = fmaf(f[k], f[k], nrm2);
    float inv = 1.0f / fmaxf(sqrtf(nrm2), EPSW);

    float4* o = reinterpret_cast<float4*>(g_fhat + ((size_t)n * BB + b) * 16);
#pragma unroll
    for (int q = 0; q < 4; q++) {
        float4 w;
        w.x = f[q * 4 + 0] * inv;
        w.y = f[q * 4 + 1] * inv;
        w.z = f[q * 4 + 2] * inv;
        w.w = f[q * 4 + 3] * inv;
        o[q] = w;
    }
}

// ---------------------------------------------------------------------------
// Kernel 0: zero the accumulators
// ---------------------------------------------------------------------------
__global__ void zero_kernel() {
    int i = blockIdx.x * blockDim.x + threadIdx.x;
    if (i < EEDGE * BB) g_acc[i] = 0.f;
}

// ---------------------------------------------------------------------------
// Kernel 2: per-warp chunk of 32 members; lane = batch b.
// Segmented (sorted edge ids) clipped-cosine accumulation with register-held
// center vector reused across a segment run; flush via atomicAdd on change.
// ---------------------------------------------------------------------------
__global__ void sim_kernel(const int* __restrict__ members,
                           const int* __restrict__ eids) {
    int warp = (blockIdx.x * blockDim.x + threadIdx.x) >> 5;
    int lane = threadIdx.x & 31;
    int m0 = warp * 32;
    if (m0 >= MEDGE) return;
    int cnt = min(32, MEDGE - m0);

    int mm = m0 + lane;
    int my_node = (mm < MEDGE) ? members[mm] : 0;
    int my_e    = (mm < MEDGE) ? eids[mm]    : -1;

    float4 v0, v1, v2, v3;
    int   cur_e = -1;
    float accs  = 0.f;

    for (int i = 0; i < cnt; i++) {
        int node = __shfl_sync(0xffffffffu, my_node, i);
        int e    = __shfl_sync(0xffffffffu, my_e, i);
        if (e != cur_e) {
            if (cur_e >= 0) atomicAdd(&g_acc[(size_t)cur_e * BB + lane], accs);
            accs = 0.f;
            const float4* pv = reinterpret_cast<const float4*>(
                g_fhat + ((size_t)e * BB + lane) * 16);
            v0 = pv[0]; v1 = pv[1]; v2 = pv[2]; v3 = pv[3];
            cur_e = e;
        }
        const float4* pu = reinterpret_cast<const float4*>(
            g_fhat + ((size_t)node * BB + lane) * 16);
        float4 u0 = pu[0], u1 = pu[1], u2 = pu[2], u3 = pu[3];

        float d = u0.x * v0.x;
        d = fmaf(u0.y, v0.y, d); d = fmaf(u0.z, v0.z, d); d = fmaf(u0.w, v0.w, d);
        d = fmaf(u1.x, v1.x, d); d = fmaf(u1.y, v1.y, d); d = fmaf(u1.z, v1.z, d);
        d = fmaf(u1.w, v1.w, d); d = fmaf(u2.x, v2.x, d); d = fmaf(u2.y, v2.y, d);
        d = fmaf(u2.z, v2.z, d); d = fmaf(u2.w, v2.w, d); d = fmaf(u3.x, v3.x, d);
        d = fmaf(u3.y, v3.y, d); d = fmaf(u3.z, v3.z, d); d = fmaf(u3.w, v3.w, d);

        d = fminf(fmaxf(d, 0.f), 1.f);
        accs += d;
    }
    if (cur_e >= 0) atomicAdd(&g_acc[(size_t)cur_e * BB + lane], accs);
}

// ---------------------------------------------------------------------------
// Kernel 3: per-b min/max normalize and scale by W
// ---------------------------------------------------------------------------
__global__ void finalize_kernel(const float* __restrict__ W,
                                const float* __restrict__ counts,
                                float* __restrict__ out) {
    int b = blockIdx.x;
    __shared__ float smn[8], smx[8];

    float mn = 1e30f, mx = -1e30f;
    for (int e = threadIdx.x; e < EEDGE; e += blockDim.x) {
        float s = g_acc[(size_t)e * BB + b] / fmaxf(counts[e], 1.f);
        mn = fminf(mn, s);
        mx = fmaxf(mx, s);
    }
#pragma unroll
    for (int o = 16; o; o >>= 1) {
        mn = fminf(mn, __shfl_xor_sync(0xffffffffu, mn, o));
        mx = fmaxf(mx, __shfl_xor_sync(0xffffffffu, mx, o));
    }
    int wid = threadIdx.x >> 5, lane = threadIdx.x & 31;
    if (lane == 0) { smn[wid] = mn; smx[wid] = mx; }
    __syncthreads();
    if (threadIdx.x == 0) {
        float a = smn[0], c = smx[0];
        for (int i = 1; i < (int)(blockDim.x >> 5); i++) {
            a = fminf(a, smn[i]);
            c = fmaxf(c, smx[i]);
        }
        smn[0] = a; smx[0] = c;
    }
    __syncthreads();
    mn = smn[0];
    mx = smx[0];
    float inv = 1.f / (mx - mn + EPSW);

    for (int e = threadIdx.x; e < EEDGE; e += blockDim.x) {
        float s = g_acc[(size_t)e * BB + b] / fmaxf(counts[e], 1.f);
        out[(size_t)b * EEDGE + e] = W[e] * (1.f + LAMW * (s - mn) * inv);
    }
}

// ---------------------------------------------------------------------------
extern "C" void kernel_launch(void* const* d_in, const int* in_sizes, int n_in,
                              void* d_out, int out_size) {
    const float* x_raw   = (const float*)d_in[0];
    const float* W       = (const float*)d_in[1];
    const int*   members = (const int*)d_in[2];
    // d_in[3] = centers (== arange(E), unused)
    const int*   eids    = (const int*)d_in[4];
    const float* counts  = (const float*)d_in[5];
    float*       out     = (float*)d_out;

    zero_kernel<<<(EEDGE * BB + 255) / 256, 256>>>();
    feat_kernel<<<(BB * NNODE + 255) / 256, 256>>>(x_raw);

    int warps  = (MEDGE + 31) / 32;
    int blocks = (warps * 32 + 255) / 256;
    sim_kernel<<<blocks, 256>>>(members, eids);

    finalize_kernel<<<BB, 256>>>(W, counts, out);
}